// round 5
// baseline (speedup 1.0000x reference)
#include <cuda_runtime.h>
#include <cuda_bf16.h>
#include <math.h>
#include <float.h>

// ---------------- problem constants ----------------
constexpr int Bv  = 2;
constexpr int Tv  = 1024;
constexpr int Lv  = 12;
constexpr int Hv  = 12;
constexpr int Dv  = 768;
constexpr int HDv = 64;
constexpr int FFv = 3072;
constexpr int Vv  = 50257;
constexpr int Mv  = Bv * Tv;          // 2048 rows
constexpr int D3v = 3 * Dv;           // 2304

// ---------------- scratch (static device memory; no allocations) ----------------
__device__ float g_x   [(size_t)Mv * Dv];
__device__ float g_h   [(size_t)Mv * Dv];
__device__ float g_qkv [(size_t)Mv * D3v];
__device__ float g_y   [(size_t)Mv * Dv];
__device__ float g_ff  [(size_t)Mv * FFv];
__device__ float g_att [(size_t)Bv * Hv * Tv * Tv];   // 96 MB
__device__ float g_nll [Mv];
__device__ float g_val [Mv];
__device__ float g_logits_fallback[(size_t)Mv * Vv];  // used only if d_out can't hold logits

// ---------------- helpers ----------------
__device__ __forceinline__ float mgelu_f(float x) {
    // NOTE: module uses 0.047715 (not the standard 0.044715)
    const float c0 = 0.7978845608028654f; // sqrt(2/pi)
    float x3 = x * x * x;
    return 0.5f * x * (1.0f + tanhf(c0 * (x + 0.047715f * x3)));
}

// ---------------- embedding ----------------
__global__ void k_embed(const int* __restrict__ idx,
                        const float* __restrict__ wte,
                        const float* __restrict__ wpe,
                        float* __restrict__ x) {
    int i = blockIdx.x * 256 + threadIdx.x;
    if (i >= Mv * Dv) return;
    int m = i / Dv, d = i % Dv;
    int t = m % Tv;
    x[i] = wte[(size_t)idx[m] * Dv + d] + wpe[(size_t)t * Dv + d];
}

// ---------------- layernorm (one block per row) ----------------
__global__ void k_ln(const float* __restrict__ x,
                     const float* __restrict__ g,
                     const float* __restrict__ b,
                     float* __restrict__ o) {
    int row = blockIdx.x;
    const float* xr = x + (size_t)row * Dv;
    __shared__ float red[256];
    int tid = threadIdx.x;

    float s = 0.f;
    for (int d = tid; d < Dv; d += 256) s += xr[d];
    red[tid] = s; __syncthreads();
    for (int st = 128; st > 0; st >>= 1) { if (tid < st) red[tid] += red[tid + st]; __syncthreads(); }
    float mean = red[0] / Dv;
    __syncthreads();

    float v = 0.f;
    for (int d = tid; d < Dv; d += 256) { float t = xr[d] - mean; v += t * t; }
    red[tid] = v; __syncthreads();
    for (int st = 128; st > 0; st >>= 1) { if (tid < st) red[tid] += red[tid + st]; __syncthreads(); }
    float inv = rsqrtf(red[0] / Dv + 1e-5f);

    float* orow = o + (size_t)row * Dv;
    for (int d = tid; d < Dv; d += 256)
        orow[d] = (xr[d] - mean) * inv * g[d] + b[d];
}

// ---------------- generic tiled SGEMM with fused epilogue ----------------
// C[M,N] = epi( A[M,K] @ W[K,N] )   epi: +bias, optional mgelu, optional +res
// M multiple of 128; K multiple of 16; N arbitrary.
// float4 B-path requires N % 4 == 0 (otherwise rows are not 16B-aligned).
#define BM 128
#define BN 128
#define BK 16
__global__ __launch_bounds__(256) void k_sgemm(
    const float* __restrict__ A, const float* __restrict__ W,
    const float* __restrict__ bias, const float* __restrict__ res,
    float* __restrict__ C, int M, int N, int K, int act) {

    __shared__ float As[BK][BM];       // As[k][m]
    __shared__ float Bs[BK][BN];       // Bs[k][n]
    int m0 = blockIdx.y * BM, n0 = blockIdx.x * BN;
    int tid = threadIdx.x;
    int tx = tid % 16, ty = tid / 16;
    bool vec_ok = ((N & 3) == 0) && (n0 + BN <= N);   // 16B-aligned rows + interior tile

    float acc[8][8];
#pragma unroll
    for (int i = 0; i < 8; i++)
#pragma unroll
        for (int j = 0; j < 8; j++) acc[i][j] = 0.f;

    // A-tile: 128 rows x 16 cols = 512 float4s; 256 threads x 2 (coalesced).
    int a_r = tid >> 2, a_c4 = (tid & 3) * 4;
    // B-tile (vector path): 16 rows x 128 cols = 512 float4s; 256 threads x 2.
    int b_r = tid >> 5, b_c4 = (tid & 31) * 4;
    // B-tile (scalar path): i = tid + 256*it -> (k = i/128, n = i%128): coalesced 4B.
    int s_k = tid >> 7, s_n = tid & 127;

    for (int k0 = 0; k0 < K; k0 += BK) {
        // ---- load A tile (coalesced float4, store transposed) ----
#pragma unroll
        for (int it = 0; it < 2; it++) {
            int m = a_r + 64 * it;
            float4 v = *(const float4*)&A[(size_t)(m0 + m) * K + k0 + a_c4];
            As[a_c4 + 0][m] = v.x;
            As[a_c4 + 1][m] = v.y;
            As[a_c4 + 2][m] = v.z;
            As[a_c4 + 3][m] = v.w;
        }
        // ---- load B tile ----
        if (vec_ok) {
#pragma unroll
            for (int it = 0; it < 2; it++) {
                int k = b_r + 8 * it;
                float4 v = *(const float4*)&W[(size_t)(k0 + k) * N + n0 + b_c4];
                *(float4*)&Bs[k][b_c4] = v;
            }
        } else {
#pragma unroll
            for (int it = 0; it < 8; it++) {
                int k = s_k + 2 * it;
                int n = n0 + s_n;
                Bs[k][s_n] = (n < N) ? W[(size_t)(k0 + k) * N + n] : 0.f;
            }
        }
        __syncthreads();
#pragma unroll
        for (int k = 0; k < BK; k++) {
            float4 a0 = *(const float4*)&As[k][ty * 8];
            float4 a1 = *(const float4*)&As[k][ty * 8 + 4];
            float4 b0 = *(const float4*)&Bs[k][tx * 8];
            float4 b1 = *(const float4*)&Bs[k][tx * 8 + 4];
            float a[8] = {a0.x, a0.y, a0.z, a0.w, a1.x, a1.y, a1.z, a1.w};
            float b[8] = {b0.x, b0.y, b0.z, b0.w, b1.x, b1.y, b1.z, b1.w};
#pragma unroll
            for (int i = 0; i < 8; i++)
#pragma unroll
                for (int j = 0; j < 8; j++) acc[i][j] += a[i] * b[j];
        }
        __syncthreads();
    }

#pragma unroll
    for (int i = 0; i < 8; i++) {
        int m = m0 + ty * 8 + i;
#pragma unroll
        for (int j = 0; j < 8; j++) {
            int n = n0 + tx * 8 + j;
            if (n < N) {
                float v = acc[i][j];
                if (bias) v += bias[n];
                if (act) v = mgelu_f(v);
                if (res) v += res[(size_t)m * N + n];
                C[(size_t)m * N + n] = v;
            }
        }
    }
}

// ---------------- attention scores: S = scale * Q K^T (causal block skip) ----------------
__global__ void k_scores(const float* __restrict__ qkv, float* __restrict__ att) {
    int bh = blockIdx.z;
    int b = bh / Hv, h = bh % Hv;
    int q0 = blockIdx.y * 16, k0 = blockIdx.x * 16;
    if (k0 > q0 + 15) return;   // fully above the diagonal
    __shared__ float Qs[16][17], Ks[16][17];
    int tx = threadIdx.x % 16, ty = threadIdx.x / 16;
    float acc = 0.f;
#pragma unroll
    for (int d0 = 0; d0 < HDv; d0 += 16) {
        Qs[ty][tx] = qkv[(size_t)(b * Tv + q0 + ty) * D3v + h * HDv + d0 + tx];
        Ks[ty][tx] = qkv[(size_t)(b * Tv + k0 + ty) * D3v + Dv + h * HDv + d0 + tx];
        __syncthreads();
#pragma unroll
        for (int d = 0; d < 16; d++) acc += Qs[ty][d] * Ks[tx][d];
        __syncthreads();
    }
    att[((size_t)bh * Tv + (q0 + ty)) * Tv + k0 + tx] = acc * 0.125f; // 1/sqrt(64)
}

// ---------------- causal row softmax (one block per (b,h,q)) ----------------
__global__ void k_attn_softmax(float* __restrict__ att) {
    int row = blockIdx.x;             // over B*H*T
    int q = row % Tv;
    float* p = att + (size_t)row * Tv;
    int n = q + 1;
    __shared__ float red[256];
    int tid = threadIdx.x;

    float mx = -FLT_MAX;
    for (int i = tid; i < n; i += 256) mx = fmaxf(mx, p[i]);
    red[tid] = mx; __syncthreads();
    for (int st = 128; st > 0; st >>= 1) { if (tid < st) red[tid] = fmaxf(red[tid], red[tid + st]); __syncthreads(); }
    mx = red[0];
    __syncthreads();

    float s = 0.f;
    for (int i = tid; i < n; i += 256) { float e = expf(p[i] - mx); p[i] = e; s += e; }
    red[tid] = s; __syncthreads();
    for (int st = 128; st > 0; st >>= 1) { if (tid < st) red[tid] += red[tid + st]; __syncthreads(); }
    float inv = 1.0f / red[0];
    for (int i = tid; i < n; i += 256) p[i] *= inv;
}

// ---------------- att @ V ----------------
__global__ void k_av(const float* __restrict__ att, const float* __restrict__ qkv,
                     float* __restrict__ y) {
    int bh = blockIdx.z;
    int b = bh / Hv, h = bh % Hv;
    int q0 = blockIdx.y * 16, d0 = blockIdx.x * 16;
    __shared__ float Ps[16][17], Vs[16][17];
    int tx = threadIdx.x % 16, ty = threadIdx.x / 16;
    float acc = 0.f;
    int kmax = q0 + 15;
    for (int k0 = 0; k0 <= kmax; k0 += 16) {
        int q = q0 + ty, k = k0 + tx;
        Ps[ty][tx] = (k <= q) ? att[((size_t)bh * Tv + q) * Tv + k] : 0.f;
        Vs[ty][tx] = qkv[(size_t)(b * Tv + k0 + ty) * D3v + 2 * Dv + h * HDv + d0 + tx];
        __syncthreads();
#pragma unroll
        for (int kk = 0; kk < 16; kk++) acc += Ps[ty][kk] * Vs[kk][tx];
        __syncthreads();
    }
    y[(size_t)(b * Tv + q0 + ty) * Dv + h * HDv + d0 + tx] = acc;
}

// ---------------- cross-entropy: per-row logsumexp ----------------
__global__ void k_nll(const float* __restrict__ logits, const int* __restrict__ targets,
                      float* __restrict__ nll, float* __restrict__ val) {
    int row = blockIdx.x;
    const float* lr = logits + (size_t)row * Vv;
    __shared__ float red[256];
    int tid = threadIdx.x;

    float mx = -FLT_MAX;
    for (int i = tid; i < Vv; i += 256) mx = fmaxf(mx, lr[i]);
    red[tid] = mx; __syncthreads();
    for (int st = 128; st > 0; st >>= 1) { if (tid < st) red[tid] = fmaxf(red[tid], red[tid + st]); __syncthreads(); }
    mx = red[0];
    __syncthreads();

    float s = 0.f;
    for (int i = tid; i < Vv; i += 256) s += expf(lr[i] - mx);
    red[tid] = s; __syncthreads();
    for (int st = 128; st > 0; st >>= 1) { if (tid < st) red[tid] += red[tid + st]; __syncthreads(); }

    if (tid == 0) {
        int tgt = targets[row];
        bool ok = (tgt >= 0);
        float lse = mx + logf(red[0]);
        nll[row] = ok ? (lse - lr[tgt]) : 0.f;
        val[row] = ok ? 1.f : 0.f;
    }
}

__global__ void k_loss(const float* __restrict__ nll, const float* __restrict__ val,
                       float* __restrict__ out) {
    __shared__ float rn[256], rv[256];
    int tid = threadIdx.x;
    float sn = 0.f, sv = 0.f;
    for (int i = tid; i < Mv; i += 256) { sn += nll[i]; sv += val[i]; }
    rn[tid] = sn; rv[tid] = sv; __syncthreads();
    for (int st = 128; st > 0; st >>= 1) {
        if (tid < st) { rn[tid] += rn[tid + st]; rv[tid] += rv[tid + st]; }
        __syncthreads();
    }
    if (tid == 0) out[0] = rn[0] / fmaxf(rv[0], 1.f);
}

// ---------------- host driver ----------------
extern "C" void kernel_launch(void* const* d_in, const int* in_sizes, int n_in,
                              void* d_out, int out_size) {
    const int*   idx     = (const int*)  d_in[0];
    const int*   targets = (const int*)  d_in[1];
    const float* wte     = (const float*)d_in[2];
    const float* wpe     = (const float*)d_in[3];
    const float* ln1_g   = (const float*)d_in[4];
    const float* ln1_b   = (const float*)d_in[5];
    const float* qkv_w   = (const float*)d_in[6];
    const float* qkv_b   = (const float*)d_in[7];
    const float* po_w    = (const float*)d_in[8];
    const float* po_b    = (const float*)d_in[9];
    const float* ln2_g   = (const float*)d_in[10];
    const float* ln2_b   = (const float*)d_in[11];
    const float* fc_w    = (const float*)d_in[12];
    const float* fc_b    = (const float*)d_in[13];
    const float* pr_w    = (const float*)d_in[14];
    const float* pr_b    = (const float*)d_in[15];
    const float* lnf_g   = (const float*)d_in[16];
    const float* lnf_b   = (const float*)d_in[17];
    const float* lm_w    = (const float*)d_in[18];
    float* out = (float*)d_out;

    float *px, *ph, *pqkv, *py, *pff, *patt, *pnll, *pval, *pfall;
    cudaGetSymbolAddress((void**)&px,   g_x);
    cudaGetSymbolAddress((void**)&ph,   g_h);
    cudaGetSymbolAddress((void**)&pqkv, g_qkv);
    cudaGetSymbolAddress((void**)&py,   g_y);
    cudaGetSymbolAddress((void**)&pff,  g_ff);
    cudaGetSymbolAddress((void**)&patt, g_att);
    cudaGetSymbolAddress((void**)&pnll, g_nll);
    cudaGetSymbolAddress((void**)&pval, g_val);
    cudaGetSymbolAddress((void**)&pfall, g_logits_fallback);

    const long long need_logits = (long long)Mv * Vv;
    float* logits = ((long long)out_size >= need_logits) ? out : pfall;
    float* loss_dst = ((long long)out_size >= need_logits + 1) ? (out + need_logits)
                    : (((long long)out_size < need_logits) ? out : nullptr);

    // embedding
    k_embed<<<(Mv * Dv + 255) / 256, 256>>>(idx, wte, wpe, px);

    dim3 gs_sm(Tv / 16, Tv / 16, Bv * Hv);
    dim3 gs_av(HDv / 16, Tv / 16, Bv * Hv);

    for (int l = 0; l < Lv; l++) {
        const float* l1g = ln1_g + (size_t)l * Dv;
        const float* l1b = ln1_b + (size_t)l * Dv;
        const float* wq  = qkv_w + (size_t)l * Dv * D3v;
        const float* bq  = qkv_b + (size_t)l * D3v;
        const float* wo  = po_w  + (size_t)l * Dv * Dv;
        const float* bo  = po_b  + (size_t)l * Dv;
        const float* l2g = ln2_g + (size_t)l * Dv;
        const float* l2b = ln2_b + (size_t)l * Dv;
        const float* wf  = fc_w  + (size_t)l * Dv * FFv;
        const float* bf  = fc_b  + (size_t)l * FFv;
        const float* wp  = pr_w  + (size_t)l * FFv * Dv;
        const float* bp  = pr_b  + (size_t)l * Dv;

        // ln1
        k_ln<<<Mv, 256>>>(px, l1g, l1b, ph);
        // qkv = h @ wq + bq
        k_sgemm<<<dim3((D3v + BN - 1) / BN, Mv / BM), 256>>>(ph, wq, bq, nullptr, pqkv, Mv, D3v, Dv, 0);
        // attention
        k_scores<<<gs_sm, 256>>>(pqkv, patt);
        k_attn_softmax<<<Bv * Hv * Tv, 256>>>(patt);
        k_av<<<gs_av, 256>>>(patt, pqkv, py);
        // x = x + y @ wo + bo
        k_sgemm<<<dim3((Dv + BN - 1) / BN, Mv / BM), 256>>>(py, wo, bo, px, px, Mv, Dv, Dv, 0);
        // ln2
        k_ln<<<Mv, 256>>>(px, l2g, l2b, ph);
        // ff = mgelu(h2 @ wf + bf)
        k_sgemm<<<dim3((FFv + BN - 1) / BN, Mv / BM), 256>>>(ph, wf, bf, nullptr, pff, Mv, FFv, Dv, 1);
        // x = x + ff @ wp + bp
        k_sgemm<<<dim3((Dv + BN - 1) / BN, Mv / BM), 256>>>(pff, wp, bp, px, px, Mv, Dv, FFv, 0);
    }

    // final layernorm + LM head
    k_ln<<<Mv, 256>>>(px, lnf_g, lnf_b, ph);
    k_sgemm<<<dim3((Vv + BN - 1) / BN, Mv / BM), 256>>>(ph, lm_w, nullptr, nullptr, logits, Mv, Vv, Dv, 0);

    // loss
    k_nll<<<Mv, 256>>>(logits, targets, pnll, pval);
    if (loss_dst) k_loss<<<1, 256>>>(pnll, pval, loss_dst);
}

// round 9
// speedup vs baseline: 1.1148x; 1.1148x over previous
#include <cuda_runtime.h>
#include <cuda_bf16.h>
#include <math.h>
#include <float.h>
#include <stdint.h>

// ---------------- problem constants ----------------
constexpr int Bv  = 2;
constexpr int Tv  = 1024;
constexpr int Lv  = 12;
constexpr int Hv  = 12;
constexpr int Dv  = 768;
constexpr int HDv = 64;
constexpr int FFv = 3072;
constexpr int Vv  = 50257;
constexpr int Mv  = Bv * Tv;          // 2048 rows
constexpr int D3v = 3 * Dv;           // 2304

// ---------------- scratch (static device memory; no allocations) ----------------
__device__ float g_x   [(size_t)Mv * Dv];
__device__ float g_h   [(size_t)Mv * Dv];
__device__ float g_qkv [(size_t)Mv * D3v];
__device__ float g_y   [(size_t)Mv * Dv];
__device__ float g_ff  [(size_t)Mv * FFv];
__device__ float g_att [(size_t)Bv * Hv * Tv * Tv];   // 96 MB
__device__ float g_nll [Mv];
__device__ float g_val [Mv];
__device__ float g_logits_fallback[(size_t)Mv * Vv];  // used only if d_out can't hold logits

// ---------------- helpers ----------------
__device__ __forceinline__ float mgelu_f(float x) {
    // NOTE: module uses 0.047715 (not the standard 0.044715)
    const float c0 = 0.7978845608028654f; // sqrt(2/pi)
    float x3 = x * x * x;
    return 0.5f * x * (1.0f + tanhf(c0 * (x + 0.047715f * x3)));
}

__device__ __forceinline__ float tf32_round(float x) {
    uint32_t u;
    asm("cvt.rna.tf32.f32 %0, %1;" : "=r"(u) : "f"(x));
    return __uint_as_float(u);
}

#define MMA_TF32(c, a0, a1, a2, a3, b0, b1)                                   \
    asm volatile(                                                             \
        "mma.sync.aligned.m16n8k8.row.col.f32.tf32.tf32.f32 "                 \
        "{%0,%1,%2,%3}, {%4,%5,%6,%7}, {%8,%9}, {%0,%1,%2,%3};"               \
        : "+f"((c)[0]), "+f"((c)[1]), "+f"((c)[2]), "+f"((c)[3])              \
        : "r"(a0), "r"(a1), "r"(a2), "r"(a3), "r"(b0), "r"(b1))

// ---------------- embedding ----------------
__global__ void k_embed(const int* __restrict__ idx,
                        const float* __restrict__ wte,
                        const float* __restrict__ wpe,
                        float* __restrict__ x) {
    int i = blockIdx.x * 256 + threadIdx.x;
    if (i >= Mv * Dv) return;
    int m = i / Dv, d = i % Dv;
    int t = m % Tv;
    x[i] = wte[(size_t)idx[m] * Dv + d] + wpe[(size_t)t * Dv + d];
}

// ---------------- layernorm (one block per row) ----------------
__global__ void k_ln(const float* __restrict__ x,
                     const float* __restrict__ g,
                     const float* __restrict__ b,
                     float* __restrict__ o) {
    int row = blockIdx.x;
    const float* xr = x + (size_t)row * Dv;
    __shared__ float red[256];
    int tid = threadIdx.x;

    float s = 0.f;
    for (int d = tid; d < Dv; d += 256) s += xr[d];
    red[tid] = s; __syncthreads();
    for (int st = 128; st > 0; st >>= 1) { if (tid < st) red[tid] += red[tid + st]; __syncthreads(); }
    float mean = red[0] / Dv;
    __syncthreads();

    float v = 0.f;
    for (int d = tid; d < Dv; d += 256) { float t = xr[d] - mean; v += t * t; }
    red[tid] = v; __syncthreads();
    for (int st = 128; st > 0; st >>= 1) { if (tid < st) red[tid] += red[tid + st]; __syncthreads(); }
    float inv = rsqrtf(red[0] / Dv + 1e-5f);

    float* orow = o + (size_t)row * Dv;
    for (int d = tid; d < Dv; d += 256)
        orow[d] = (xr[d] - mean) * inv * g[d] + b[d];
}

// ---------------- 3xTF32 tensor-core GEMM with fused epilogue ----------------
// C[M,N] = epi( A[M,K] @ W[K,N] )   epi: +bias, optional mgelu, optional +res
// M multiple of 128; K multiple of 16; N arbitrary.
// Hi/lo tf32 split (3 MMAs) keeps ~fp32 precision.
#define BM 128
#define BN 128
#define BK 16
#define SPAD 4
__global__ __launch_bounds__(256) void k_sgemm(
    const float* __restrict__ A, const float* __restrict__ W,
    const float* __restrict__ bias, const float* __restrict__ res,
    float* __restrict__ C, int M, int N, int K, int act) {

    __shared__ float Ah[BK][BM + SPAD], Al[BK][BM + SPAD];
    __shared__ float Bh[BK][BN + SPAD], Bl[BK][BN + SPAD];

    int m0 = blockIdx.y * BM, n0 = blockIdx.x * BN;
    int tid  = threadIdx.x;
    int lane = tid & 31, warp = tid >> 5;
    int warp_m = warp & 3;          // 0..3 -> 32-row slab
    int warp_n = warp >> 2;         // 0..1 -> 64-col slab
    int rowq = lane >> 2;           // 0..7
    int kr   = lane & 3;            // 0..3
    bool vec_ok = ((N & 3) == 0) && (n0 + BN <= N);

    float acc[2][8][4];
#pragma unroll
    for (int i = 0; i < 2; i++)
#pragma unroll
        for (int j = 0; j < 8; j++)
#pragma unroll
            for (int q = 0; q < 4; q++) acc[i][j][q] = 0.f;

    // gmem->smem mappings (identical to verified fp32 version)
    int a_r = tid >> 2, a_c4 = (tid & 3) * 4;
    int b_r = tid >> 5, b_c4 = (tid & 31) * 4;
    int s_k = tid >> 7, s_n = tid & 127;

    for (int k0 = 0; k0 < K; k0 += BK) {
        // ---- A tile: coalesced float4, transposed store, hi/lo split ----
#pragma unroll
        for (int it = 0; it < 2; it++) {
            int m = a_r + 64 * it;
            float4 v = *(const float4*)&A[(size_t)(m0 + m) * K + k0 + a_c4];
            float c[4] = {v.x, v.y, v.z, v.w};
#pragma unroll
            for (int j = 0; j < 4; j++) {
                float hi = tf32_round(c[j]);
                Ah[a_c4 + j][m] = hi;
                Al[a_c4 + j][m] = tf32_round(c[j] - hi);
            }
        }
        // ---- B tile ----
        if (vec_ok) {
#pragma unroll
            for (int it = 0; it < 2; it++) {
                int k = b_r + 8 * it;
                float4 v = *(const float4*)&W[(size_t)(k0 + k) * N + n0 + b_c4];
                float c[4] = {v.x, v.y, v.z, v.w};
#pragma unroll
                for (int j = 0; j < 4; j++) {
                    float hi = tf32_round(c[j]);
                    Bh[k][b_c4 + j] = hi;
                    Bl[k][b_c4 + j] = tf32_round(c[j] - hi);
                }
            }
        } else {
#pragma unroll
            for (int it = 0; it < 8; it++) {
                int k = s_k + 2 * it;
                int n = n0 + s_n;
                float w = (n < N) ? W[(size_t)(k0 + k) * N + n] : 0.f;
                float hi = tf32_round(w);
                Bh[k][s_n] = hi;
                Bl[k][s_n] = tf32_round(w - hi);
            }
        }
        __syncthreads();

#pragma unroll
        for (int kk = 0; kk < BK; kk += 8) {
            // A fragments (hi & lo) for both 16-row m-tiles
            uint32_t ahf[2][4], alf[2][4];
#pragma unroll
            for (int mt = 0; mt < 2; mt++) {
                int mb = warp_m * 32 + mt * 16 + rowq;
                ahf[mt][0] = __float_as_uint(Ah[kk + kr    ][mb    ]);
                ahf[mt][1] = __float_as_uint(Ah[kk + kr    ][mb + 8]);
                ahf[mt][2] = __float_as_uint(Ah[kk + kr + 4][mb    ]);
                ahf[mt][3] = __float_as_uint(Ah[kk + kr + 4][mb + 8]);
                alf[mt][0] = __float_as_uint(Al[kk + kr    ][mb    ]);
                alf[mt][1] = __float_as_uint(Al[kk + kr    ][mb + 8]);
                alf[mt][2] = __float_as_uint(Al[kk + kr + 4][mb    ]);
                alf[mt][3] = __float_as_uint(Al[kk + kr + 4][mb + 8]);
            }
#pragma unroll
            for (int nt = 0; nt < 8; nt++) {
                int nb = warp_n * 64 + nt * 8 + rowq;
                uint32_t bh0 = __float_as_uint(Bh[kk + kr    ][nb]);
                uint32_t bh1 = __float_as_uint(Bh[kk + kr + 4][nb]);
                uint32_t bl0 = __float_as_uint(Bl[kk + kr    ][nb]);
                uint32_t bl1 = __float_as_uint(Bl[kk + kr + 4][nb]);
#pragma unroll
                for (int mt = 0; mt < 2; mt++) {
                    MMA_TF32(acc[mt][nt], ahf[mt][0], ahf[mt][1], ahf[mt][2], ahf[mt][3], bh0, bh1);
                    MMA_TF32(acc[mt][nt], ahf[mt][0], ahf[mt][1], ahf[mt][2], ahf[mt][3], bl0, bl1);
                    MMA_TF32(acc[mt][nt], alf[mt][0], alf[mt][1], alf[mt][2], alf[mt][3], bh0, bh1);
                }
            }
        }
        __syncthreads();
    }

    // ---- epilogue: m16n8 accumulator layout ----
    int colq = (lane & 3) * 2;
#pragma unroll
    for (int mt = 0; mt < 2; mt++) {
        int r0 = m0 + warp_m * 32 + mt * 16 + rowq;
#pragma unroll
        for (int nt = 0; nt < 8; nt++) {
            int c0 = n0 + warp_n * 64 + nt * 8 + colq;
#pragma unroll
            for (int half = 0; half < 2; half++) {      // 0: rows r0, 1: rows r0+8
                int r = r0 + 8 * half;
#pragma unroll
                for (int cc = 0; cc < 2; cc++) {        // col c0 / c0+1
                    int c = c0 + cc;
                    if (c < N) {
                        float v = acc[mt][nt][half * 2 + cc];
                        if (bias) v += bias[c];
                        if (act) v = mgelu_f(v);
                        if (res) v += res[(size_t)r * N + c];
                        C[(size_t)r * N + c] = v;
                    }
                }
            }
        }
    }
}

// ---------------- attention scores: S = scale * Q K^T (causal block skip) ----------------
__global__ void k_scores(const float* __restrict__ qkv, float* __restrict__ att) {
    int bh = blockIdx.z;
    int b = bh / Hv, h = bh % Hv;
    int q0 = blockIdx.y * 16, k0 = blockIdx.x * 16;
    if (k0 > q0 + 15) return;   // fully above the diagonal
    __shared__ float Qs[16][17], Ks[16][17];
    int tx = threadIdx.x % 16, ty = threadIdx.x / 16;
    float acc = 0.f;
#pragma unroll
    for (int d0 = 0; d0 < HDv; d0 += 16) {
        Qs[ty][tx] = qkv[(size_t)(b * Tv + q0 + ty) * D3v + h * HDv + d0 + tx];
        Ks[ty][tx] = qkv[(size_t)(b * Tv + k0 + ty) * D3v + Dv + h * HDv + d0 + tx];
        __syncthreads();
#pragma unroll
        for (int d = 0; d < 16; d++) acc += Qs[ty][d] * Ks[tx][d];
        __syncthreads();
    }
    att[((size_t)bh * Tv + (q0 + ty)) * Tv + k0 + tx] = acc * 0.125f; // 1/sqrt(64)
}

// ---------------- causal row softmax (one block per (b,h,q)) ----------------
__global__ void k_attn_softmax(float* __restrict__ att) {
    int row = blockIdx.x;             // over B*H*T
    int q = row % Tv;
    float* p = att + (size_t)row * Tv;
    int n = q + 1;
    __shared__ float red[256];
    int tid = threadIdx.x;

    float mx = -FLT_MAX;
    for (int i = tid; i < n; i += 256) mx = fmaxf(mx, p[i]);
    red[tid] = mx; __syncthreads();
    for (int st = 128; st > 0; st >>= 1) { if (tid < st) red[tid] = fmaxf(red[tid], red[tid + st]); __syncthreads(); }
    mx = red[0];
    __syncthreads();

    float s = 0.f;
    for (int i = tid; i < n; i += 256) { float e = expf(p[i] - mx); p[i] = e; s += e; }
    red[tid] = s; __syncthreads();
    for (int st = 128; st > 0; st >>= 1) { if (tid < st) red[tid] += red[tid + st]; __syncthreads(); }
    float inv = 1.0f / red[0];
    for (int i = tid; i < n; i += 256) p[i] *= inv;
}

// ---------------- att @ V ----------------
__global__ void k_av(const float* __restrict__ att, const float* __restrict__ qkv,
                     float* __restrict__ y) {
    int bh = blockIdx.z;
    int b = bh / Hv, h = bh % Hv;
    int q0 = blockIdx.y * 16, d0 = blockIdx.x * 16;
    __shared__ float Ps[16][17], Vs[16][17];
    int tx = threadIdx.x % 16, ty = threadIdx.x / 16;
    float acc = 0.f;
    int kmax = q0 + 15;
    for (int k0 = 0; k0 <= kmax; k0 += 16) {
        int q = q0 + ty, k = k0 + tx;
        Ps[ty][tx] = (k <= q) ? att[((size_t)bh * Tv + q) * Tv + k] : 0.f;
        Vs[ty][tx] = qkv[(size_t)(b * Tv + k0 + ty) * D3v + 2 * Dv + h * HDv + d0 + tx];
        __syncthreads();
#pragma unroll
        for (int kk = 0; kk < 16; kk++) acc += Ps[ty][kk] * Vs[kk][tx];
        __syncthreads();
    }
    y[(size_t)(b * Tv + q0 + ty) * Dv + h * HDv + d0 + tx] = acc;
}

// ---------------- cross-entropy: per-row logsumexp ----------------
__global__ void k_nll(const float* __restrict__ logits, const int* __restrict__ targets,
                      float* __restrict__ nll, float* __restrict__ val) {
    int row = blockIdx.x;
    const float* lr = logits + (size_t)row * Vv;
    __shared__ float red[256];
    int tid = threadIdx.x;

    float mx = -FLT_MAX;
    for (int i = tid; i < Vv; i += 256) mx = fmaxf(mx, lr[i]);
    red[tid] = mx; __syncthreads();
    for (int st = 128; st > 0; st >>= 1) { if (tid < st) red[tid] = fmaxf(red[tid], red[tid + st]); __syncthreads(); }
    mx = red[0];
    __syncthreads();

    float s = 0.f;
    for (int i = tid; i < Vv; i += 256) s += expf(lr[i] - mx);
    red[tid] = s; __syncthreads();
    for (int st = 128; st > 0; st >>= 1) { if (tid < st) red[tid] += red[tid + st]; __syncthreads(); }

    if (tid == 0) {
        int tgt = targets[row];
        bool ok = (tgt >= 0);
        float lse = mx + logf(red[0]);
        nll[row] = ok ? (lse - lr[tgt]) : 0.f;
        val[row] = ok ? 1.f : 0.f;
    }
}

__global__ void k_loss(const float* __restrict__ nll, const float* __restrict__ val,
                       float* __restrict__ out) {
    __shared__ float rn[256], rv[256];
    int tid = threadIdx.x;
    float sn = 0.f, sv = 0.f;
    for (int i = tid; i < Mv; i += 256) { sn += nll[i]; sv += val[i]; }
    rn[tid] = sn; rv[tid] = sv; __syncthreads();
    for (int st = 128; st > 0; st >>= 1) {
        if (tid < st) { rn[tid] += rn[tid + st]; rv[tid] += rv[tid + st]; }
        __syncthreads();
    }
    if (tid == 0) out[0] = rn[0] / fmaxf(rv[0], 1.f);
}

// ---------------- host driver ----------------
extern "C" void kernel_launch(void* const* d_in, const int* in_sizes, int n_in,
                              void* d_out, int out_size) {
    const int*   idx     = (const int*)  d_in[0];
    const int*   targets = (const int*)  d_in[1];
    const float* wte     = (const float*)d_in[2];
    const float* wpe     = (const float*)d_in[3];
    const float* ln1_g   = (const float*)d_in[4];
    const float* ln1_b   = (const float*)d_in[5];
    const float* qkv_w   = (const float*)d_in[6];
    const float* qkv_b   = (const float*)d_in[7];
    const float* po_w    = (const float*)d_in[8];
    const float* po_b    = (const float*)d_in[9];
    const float* ln2_g   = (const float*)d_in[10];
    const float* ln2_b   = (const float*)d_in[11];
    const float* fc_w    = (const float*)d_in[12];
    const float* fc_b    = (const float*)d_in[13];
    const float* pr_w    = (const float*)d_in[14];
    const float* pr_b    = (const float*)d_in[15];
    const float* lnf_g   = (const float*)d_in[16];
    const float* lnf_b   = (const float*)d_in[17];
    const float* lm_w    = (const float*)d_in[18];
    float* out = (float*)d_out;

    float *px, *ph, *pqkv, *py, *pff, *patt, *pnll, *pval, *pfall;
    cudaGetSymbolAddress((void**)&px,   g_x);
    cudaGetSymbolAddress((void**)&ph,   g_h);
    cudaGetSymbolAddress((void**)&pqkv, g_qkv);
    cudaGetSymbolAddress((void**)&py,   g_y);
    cudaGetSymbolAddress((void**)&pff,  g_ff);
    cudaGetSymbolAddress((void**)&patt, g_att);
    cudaGetSymbolAddress((void**)&pnll, g_nll);
    cudaGetSymbolAddress((void**)&pval, g_val);
    cudaGetSymbolAddress((void**)&pfall, g_logits_fallback);

    const long long need_logits = (long long)Mv * Vv;
    float* logits = ((long long)out_size >= need_logits) ? out : pfall;
    float* loss_dst = ((long long)out_size >= need_logits + 1) ? (out + need_logits)
                    : (((long long)out_size < need_logits) ? out : nullptr);

    // embedding
    k_embed<<<(Mv * Dv + 255) / 256, 256>>>(idx, wte, wpe, px);

    dim3 gs_sm(Tv / 16, Tv / 16, Bv * Hv);
    dim3 gs_av(HDv / 16, Tv / 16, Bv * Hv);

    for (int l = 0; l < Lv; l++) {
        const float* l1g = ln1_g + (size_t)l * Dv;
        const float* l1b = ln1_b + (size_t)l * Dv;
        const float* wq  = qkv_w + (size_t)l * Dv * D3v;
        const float* bq  = qkv_b + (size_t)l * D3v;
        const float* wo  = po_w  + (size_t)l * Dv * Dv;
        const float* bo  = po_b  + (size_t)l * Dv;
        const float* l2g = ln2_g + (size_t)l * Dv;
        const float* l2b = ln2_b + (size_t)l * Dv;
        const float* wf  = fc_w  + (size_t)l * Dv * FFv;
        const float* bf  = fc_b  + (size_t)l * FFv;
        const float* wp  = pr_w  + (size_t)l * FFv * Dv;
        const float* bp  = pr_b  + (size_t)l * Dv;

        // ln1
        k_ln<<<Mv, 256>>>(px, l1g, l1b, ph);
        // qkv = h @ wq + bq
        k_sgemm<<<dim3((D3v + BN - 1) / BN, Mv / BM), 256>>>(ph, wq, bq, nullptr, pqkv, Mv, D3v, Dv, 0);
        // attention
        k_scores<<<gs_sm, 256>>>(pqkv, patt);
        k_attn_softmax<<<Bv * Hv * Tv, 256>>>(patt);
        k_av<<<gs_av, 256>>>(patt, pqkv, py);
        // x = x + y @ wo + bo
        k_sgemm<<<dim3((Dv + BN - 1) / BN, Mv / BM), 256>>>(py, wo, bo, px, px, Mv, Dv, Dv, 0);
        // ln2
        k_ln<<<Mv, 256>>>(px, l2g, l2b, ph);
        // ff = mgelu(h2 @ wf + bf)
        k_sgemm<<<dim3((FFv + BN - 1) / BN, Mv / BM), 256>>>(ph, wf, bf, nullptr, pff, Mv, FFv, Dv, 1);
        // x = x + ff @ wp + bp
        k_sgemm<<<dim3((Dv + BN - 1) / BN, Mv / BM), 256>>>(pff, wp, bp, px, px, Mv, Dv, FFv, 0);
    }

    // final layernorm + LM head
    k_ln<<<Mv, 256>>>(px, lnf_g, lnf_b, ph);
    k_sgemm<<<dim3((Vv + BN - 1) / BN, Mv / BM), 256>>>(ph, lm_w, nullptr, nullptr, logits, Mv, Vv, Dv, 0);

    // loss
    k_nll<<<Mv, 256>>>(logits, targets, pnll, pval);
    if (loss_dst) k_loss<<<1, 256>>>(pnll, pval, loss_dst);
}

// round 14
// speedup vs baseline: 1.3668x; 1.2260x over previous
#include <cuda_runtime.h>
#include <cuda_bf16.h>
#include <math.h>
#include <float.h>
#include <stdint.h>

// ---------------- problem constants ----------------
constexpr int Bv  = 2;
constexpr int Tv  = 1024;
constexpr int Lv  = 12;
constexpr int Hv  = 12;
constexpr int Dv  = 768;
constexpr int HDv = 64;
constexpr int FFv = 3072;
constexpr int Vv  = 50257;
constexpr int Mv  = Bv * Tv;          // 2048 rows
constexpr int D3v = 3 * Dv;           // 2304

// ---------------- scratch (static device memory; no allocations) ----------------
__device__ float g_x   [(size_t)Mv * Dv];
__device__ float g_h   [(size_t)Mv * Dv];
__device__ float g_qkv [(size_t)Mv * D3v];
__device__ float g_y   [(size_t)Mv * Dv];
__device__ float g_ff  [(size_t)Mv * FFv];
__device__ float g_nll [Mv];
__device__ float g_val [Mv];
__device__ float g_logits_fallback[(size_t)Mv * Vv];  // used only if d_out can't hold logits

// ---------------- helpers ----------------
__device__ __forceinline__ float mgelu_f(float x) {
    // NOTE: module uses 0.047715 (not the standard 0.044715)
    const float c0 = 0.7978845608028654f; // sqrt(2/pi)
    float x3 = x * x * x;
    return 0.5f * x * (1.0f + tanhf(c0 * (x + 0.047715f * x3)));
}

__device__ __forceinline__ float tf32_round(float x) {
    uint32_t u;
    asm("cvt.rna.tf32.f32 %0, %1;" : "=r"(u) : "f"(x));
    return __uint_as_float(u);
}

#define MMA_TF32(c, a0, a1, a2, a3, b0, b1)                                   \
    asm volatile(                                                             \
        "mma.sync.aligned.m16n8k8.row.col.f32.tf32.tf32.f32 "                 \
        "{%0,%1,%2,%3}, {%4,%5,%6,%7}, {%8,%9}, {%0,%1,%2,%3};"               \
        : "+f"((c)[0]), "+f"((c)[1]), "+f"((c)[2]), "+f"((c)[3])              \
        : "r"(a0), "r"(a1), "r"(a2), "r"(a3), "r"(b0), "r"(b1))

// ---------------- embedding ----------------
__global__ void k_embed(const int* __restrict__ idx,
                        const float* __restrict__ wte,
                        const float* __restrict__ wpe,
                        float* __restrict__ x) {
    int i = blockIdx.x * 256 + threadIdx.x;
    if (i >= Mv * Dv) return;
    int m = i / Dv, d = i % Dv;
    int t = m % Tv;
    x[i] = wte[(size_t)idx[m] * Dv + d] + wpe[(size_t)t * Dv + d];
}

// ---------------- layernorm (one block per row) ----------------
__global__ void k_ln(const float* __restrict__ x,
                     const float* __restrict__ g,
                     const float* __restrict__ b,
                     float* __restrict__ o) {
    int row = blockIdx.x;
    const float* xr = x + (size_t)row * Dv;
    __shared__ float red[256];
    int tid = threadIdx.x;

    float s = 0.f;
    for (int d = tid; d < Dv; d += 256) s += xr[d];
    red[tid] = s; __syncthreads();
    for (int st = 128; st > 0; st >>= 1) { if (tid < st) red[tid] += red[tid + st]; __syncthreads(); }
    float mean = red[0] / Dv;
    __syncthreads();

    float v = 0.f;
    for (int d = tid; d < Dv; d += 256) { float t = xr[d] - mean; v += t * t; }
    red[tid] = v; __syncthreads();
    for (int st = 128; st > 0; st >>= 1) { if (tid < st) red[tid] += red[tid + st]; __syncthreads(); }
    float inv = rsqrtf(red[0] / Dv + 1e-5f);

    float* orow = o + (size_t)row * Dv;
    for (int d = tid; d < Dv; d += 256)
        orow[d] = (xr[d] - mean) * inv * g[d] + b[d];
}

// ---------------- 3xTF32 tensor-core GEMM with fused epilogue ----------------
// C[M,N] = epi( A[M,K] @ W[K,N] )   epi: +bias, optional mgelu, optional +res
#define BM 128
#define BN 128
#define BK 16
#define SPAD 4
__global__ __launch_bounds__(256) void k_sgemm(
    const float* __restrict__ A, const float* __restrict__ W,
    const float* __restrict__ bias, const float* __restrict__ res,
    float* __restrict__ C, int M, int N, int K, int act) {

    __shared__ float Ah[BK][BM + SPAD], Al[BK][BM + SPAD];
    __shared__ float Bh[BK][BN + SPAD], Bl[BK][BN + SPAD];

    int m0 = blockIdx.y * BM, n0 = blockIdx.x * BN;
    int tid  = threadIdx.x;
    int lane = tid & 31, warp = tid >> 5;
    int warp_m = warp & 3;
    int warp_n = warp >> 2;
    int rowq = lane >> 2;
    int kr   = lane & 3;
    bool vec_ok = ((N & 3) == 0) && (n0 + BN <= N);

    float acc[2][8][4];
#pragma unroll
    for (int i = 0; i < 2; i++)
#pragma unroll
        for (int j = 0; j < 8; j++)
#pragma unroll
            for (int q = 0; q < 4; q++) acc[i][j][q] = 0.f;

    int a_r = tid >> 2, a_c4 = (tid & 3) * 4;
    int b_r = tid >> 5, b_c4 = (tid & 31) * 4;
    int s_k = tid >> 7, s_n = tid & 127;

    for (int k0 = 0; k0 < K; k0 += BK) {
#pragma unroll
        for (int it = 0; it < 2; it++) {
            int m = a_r + 64 * it;
            float4 v = *(const float4*)&A[(size_t)(m0 + m) * K + k0 + a_c4];
            float c[4] = {v.x, v.y, v.z, v.w};
#pragma unroll
            for (int j = 0; j < 4; j++) {
                float hi = tf32_round(c[j]);
                Ah[a_c4 + j][m] = hi;
                Al[a_c4 + j][m] = tf32_round(c[j] - hi);
            }
        }
        if (vec_ok) {
#pragma unroll
            for (int it = 0; it < 2; it++) {
                int k = b_r + 8 * it;
                float4 v = *(const float4*)&W[(size_t)(k0 + k) * N + n0 + b_c4];
                float c[4] = {v.x, v.y, v.z, v.w};
#pragma unroll
                for (int j = 0; j < 4; j++) {
                    float hi = tf32_round(c[j]);
                    Bh[k][b_c4 + j] = hi;
                    Bl[k][b_c4 + j] = tf32_round(c[j] - hi);
                }
            }
        } else {
#pragma unroll
            for (int it = 0; it < 8; it++) {
                int k = s_k + 2 * it;
                int n = n0 + s_n;
                float w = (n < N) ? W[(size_t)(k0 + k) * N + n] : 0.f;
                float hi = tf32_round(w);
                Bh[k][s_n] = hi;
                Bl[k][s_n] = tf32_round(w - hi);
            }
        }
        __syncthreads();

#pragma unroll
        for (int kk = 0; kk < BK; kk += 8) {
            uint32_t ahf[2][4], alf[2][4];
#pragma unroll
            for (int mt = 0; mt < 2; mt++) {
                int mb = warp_m * 32 + mt * 16 + rowq;
                ahf[mt][0] = __float_as_uint(Ah[kk + kr    ][mb    ]);
                ahf[mt][1] = __float_as_uint(Ah[kk + kr    ][mb + 8]);
                ahf[mt][2] = __float_as_uint(Ah[kk + kr + 4][mb    ]);
                ahf[mt][3] = __float_as_uint(Ah[kk + kr + 4][mb + 8]);
                alf[mt][0] = __float_as_uint(Al[kk + kr    ][mb    ]);
                alf[mt][1] = __float_as_uint(Al[kk + kr    ][mb + 8]);
                alf[mt][2] = __float_as_uint(Al[kk + kr + 4][mb    ]);
                alf[mt][3] = __float_as_uint(Al[kk + kr + 4][mb + 8]);
            }
#pragma unroll
            for (int nt = 0; nt < 8; nt++) {
                int nb = warp_n * 64 + nt * 8 + rowq;
                uint32_t bh0 = __float_as_uint(Bh[kk + kr    ][nb]);
                uint32_t bh1 = __float_as_uint(Bh[kk + kr + 4][nb]);
                uint32_t bl0 = __float_as_uint(Bl[kk + kr    ][nb]);
                uint32_t bl1 = __float_as_uint(Bl[kk + kr + 4][nb]);
#pragma unroll
                for (int mt = 0; mt < 2; mt++) {
                    MMA_TF32(acc[mt][nt], ahf[mt][0], ahf[mt][1], ahf[mt][2], ahf[mt][3], bh0, bh1);
                    MMA_TF32(acc[mt][nt], ahf[mt][0], ahf[mt][1], ahf[mt][2], ahf[mt][3], bl0, bl1);
                    MMA_TF32(acc[mt][nt], alf[mt][0], alf[mt][1], alf[mt][2], alf[mt][3], bh0, bh1);
                }
            }
        }
        __syncthreads();
    }

    int colq = (lane & 3) * 2;
#pragma unroll
    for (int mt = 0; mt < 2; mt++) {
        int r0 = m0 + warp_m * 32 + mt * 16 + rowq;
#pragma unroll
        for (int nt = 0; nt < 8; nt++) {
            int c0 = n0 + warp_n * 64 + nt * 8 + colq;
#pragma unroll
            for (int half = 0; half < 2; half++) {
                int r = r0 + 8 * half;
#pragma unroll
                for (int cc = 0; cc < 2; cc++) {
                    int c = c0 + cc;
                    if (c < N) {
                        float v = acc[mt][nt][half * 2 + cc];
                        if (bias) v += bias[c];
                        if (act) v = mgelu_f(v);
                        if (res) v += res[(size_t)r * N + c];
                        C[(size_t)r * N + c] = v;
                    }
                }
            }
        }
    }
}

// ---------------- fused flash attention (fp32) ----------------
// One CTA per (64-row q-block, b*h). qkv: [M, 3D]; y: [M, D].
// Tiles stride 64 -> static smem exactly 48KB. Inner-loop LDS: float4
// broadcast (Qt/Pt) or 256B-contiguous (Kt/Vs) -> conflict-free.
__global__ __launch_bounds__(256) void k_flash(const float* __restrict__ qkv,
                                               float* __restrict__ y) {
    __shared__ float Qt[64][64];   // [d][m]
    __shared__ float KPt[64][64];  // K phase: [d][n]; P phase: [n][m]
    __shared__ float Vs[64][64];   // [n][d]

    int bh = blockIdx.y;
    int b = bh / Hv, h = bh % Hv;
    int qb = gridDim.x - 1 - blockIdx.x;   // big blocks first
    int tid = threadIdx.x;
    int tx = tid & 15, ty = tid >> 4;

    int lr = tid >> 2;              // load row 0..63
    int lc = (tid & 3) * 16;        // 16-col chunk

    // load Q block transposed (once)
    {
        const float* src = qkv + (size_t)(b * Tv + qb * 64 + lr) * D3v + h * HDv;
#pragma unroll
        for (int j = 0; j < 4; j++) {
            float4 v = *(const float4*)&src[lc + j * 4];
            Qt[lc + j * 4 + 0][lr] = v.x;
            Qt[lc + j * 4 + 1][lr] = v.y;
            Qt[lc + j * 4 + 2][lr] = v.z;
            Qt[lc + j * 4 + 3][lr] = v.w;
        }
    }

    float O[4][4];
    float m_i[4], l_i[4];
#pragma unroll
    for (int i = 0; i < 4; i++) {
        m_i[i] = -FLT_MAX; l_i[i] = 0.f;
#pragma unroll
        for (int j = 0; j < 4; j++) O[i][j] = 0.f;
    }

    for (int kb = 0; kb <= qb; kb++) {
        // load K (transposed) and V (direct)
        {
            const float* ks = qkv + (size_t)(b * Tv + kb * 64 + lr) * D3v + Dv + h * HDv;
            const float* vs = qkv + (size_t)(b * Tv + kb * 64 + lr) * D3v + 2 * Dv + h * HDv;
#pragma unroll
            for (int j = 0; j < 4; j++) {
                float4 kv = *(const float4*)&ks[lc + j * 4];
                KPt[lc + j * 4 + 0][lr] = kv.x;
                KPt[lc + j * 4 + 1][lr] = kv.y;
                KPt[lc + j * 4 + 2][lr] = kv.z;
                KPt[lc + j * 4 + 3][lr] = kv.w;
                *(float4*)&Vs[lr][lc + j * 4] = *(const float4*)&vs[lc + j * 4];
            }
        }
        __syncthreads();

        // S = Q K^T
        float S[4][4];
#pragma unroll
        for (int i = 0; i < 4; i++)
#pragma unroll
            for (int j = 0; j < 4; j++) S[i][j] = 0.f;
        for (int kk = 0; kk < 64; kk++) {
            float4 a4 = *(const float4*)&Qt[kk][ty * 4];
            float4 b4 = *(const float4*)&KPt[kk][tx * 4];
            float a[4] = {a4.x, a4.y, a4.z, a4.w};
            float bb[4] = {b4.x, b4.y, b4.z, b4.w};
#pragma unroll
            for (int i = 0; i < 4; i++)
#pragma unroll
                for (int j = 0; j < 4; j++) S[i][j] += a[i] * bb[j];
        }

        // scale + causal mask (diagonal block only)
#pragma unroll
        for (int i = 0; i < 4; i++)
#pragma unroll
            for (int j = 0; j < 4; j++) {
                float s = S[i][j] * 0.125f;   // 1/sqrt(64)
                if (kb == qb && (tx * 4 + j) > (ty * 4 + i)) s = -1e30f;
                S[i][j] = s;
            }

        // online softmax update
#pragma unroll
        for (int i = 0; i < 4; i++) {
            float mx = fmaxf(fmaxf(S[i][0], S[i][1]), fmaxf(S[i][2], S[i][3]));
#pragma unroll
            for (int off = 8; off > 0; off >>= 1)
                mx = fmaxf(mx, __shfl_xor_sync(0xffffffffu, mx, off));
            float m_new = fmaxf(m_i[i], mx);
            float corr = expf(m_i[i] - m_new);
            float rs = 0.f;
#pragma unroll
            for (int j = 0; j < 4; j++) {
                float p = expf(S[i][j] - m_new);
                S[i][j] = p;
                rs += p;
            }
#pragma unroll
            for (int off = 8; off > 0; off >>= 1)
                rs += __shfl_xor_sync(0xffffffffu, rs, off);
            l_i[i] = l_i[i] * corr + rs;
            m_i[i] = m_new;
#pragma unroll
            for (int j = 0; j < 4; j++) O[i][j] *= corr;
        }
        __syncthreads();   // all done reading K

        // store P transposed into K tile space: KPt[n][m]
#pragma unroll
        for (int i = 0; i < 4; i++)
#pragma unroll
            for (int j = 0; j < 4; j++)
                KPt[tx * 4 + j][ty * 4 + i] = S[i][j];
        __syncthreads();

        // O += P @ V
        for (int kk = 0; kk < 64; kk++) {
            float4 p4 = *(const float4*)&KPt[kk][ty * 4];
            float4 v4 = *(const float4*)&Vs[kk][tx * 4];
            float p[4] = {p4.x, p4.y, p4.z, p4.w};
            float vv[4] = {v4.x, v4.y, v4.z, v4.w};
#pragma unroll
            for (int i = 0; i < 4; i++)
#pragma unroll
                for (int j = 0; j < 4; j++) O[i][j] += p[i] * vv[j];
        }
        __syncthreads();   // before next tile load
    }

    // write output
#pragma unroll
    for (int i = 0; i < 4; i++) {
        float inv = 1.0f / l_i[i];
        int row = b * Tv + qb * 64 + ty * 4 + i;
#pragma unroll
        for (int j = 0; j < 4; j++)
            y[(size_t)row * Dv + h * HDv + tx * 4 + j] = O[i][j] * inv;
    }
}

// ---------------- cross-entropy: per-row logsumexp ----------------
__global__ void k_nll(const float* __restrict__ logits, const int* __restrict__ targets,
                      float* __restrict__ nll, float* __restrict__ val) {
    int row = blockIdx.x;
    const float* lr = logits + (size_t)row * Vv;
    __shared__ float red[256];
    int tid = threadIdx.x;

    float mx = -FLT_MAX;
    for (int i = tid; i < Vv; i += 256) mx = fmaxf(mx, lr[i]);
    red[tid] = mx; __syncthreads();
    for (int st = 128; st > 0; st >>= 1) { if (tid < st) red[tid] = fmaxf(red[tid], red[tid + st]); __syncthreads(); }
    mx = red[0];
    __syncthreads();

    float s = 0.f;
    for (int i = tid; i < Vv; i += 256) s += expf(lr[i] - mx);
    red[tid] = s; __syncthreads();
    for (int st = 128; st > 0; st >>= 1) { if (tid < st) red[tid] += red[tid + st]; __syncthreads(); }

    if (tid == 0) {
        int tgt = targets[row];
        bool ok = (tgt >= 0);
        float lse = mx + logf(red[0]);
        nll[row] = ok ? (lse - lr[tgt]) : 0.f;
        val[row] = ok ? 1.f : 0.f;
    }
}

__global__ void k_loss(const float* __restrict__ nll, const float* __restrict__ val,
                       float* __restrict__ out) {
    __shared__ float rn[256], rv[256];
    int tid = threadIdx.x;
    float sn = 0.f, sv = 0.f;
    for (int i = tid; i < Mv; i += 256) { sn += nll[i]; sv += val[i]; }
    rn[tid] = sn; rv[tid] = sv; __syncthreads();
    for (int st = 128; st > 0; st >>= 1) {
        if (tid < st) { rn[tid] += rn[tid + st]; rv[tid] += rv[tid + st]; }
        __syncthreads();
    }
    if (tid == 0) out[0] = rn[0] / fmaxf(rv[0], 1.f);
}

// ---------------- host driver ----------------
extern "C" void kernel_launch(void* const* d_in, const int* in_sizes, int n_in,
                              void* d_out, int out_size) {
    const int*   idx     = (const int*)  d_in[0];
    const int*   targets = (const int*)  d_in[1];
    const float* wte     = (const float*)d_in[2];
    const float* wpe     = (const float*)d_in[3];
    const float* ln1_g   = (const float*)d_in[4];
    const float* ln1_b   = (const float*)d_in[5];
    const float* qkv_w   = (const float*)d_in[6];
    const float* qkv_b   = (const float*)d_in[7];
    const float* po_w    = (const float*)d_in[8];
    const float* po_b    = (const float*)d_in[9];
    const float* ln2_g   = (const float*)d_in[10];
    const float* ln2_b   = (const float*)d_in[11];
    const float* fc_w    = (const float*)d_in[12];
    const float* fc_b    = (const float*)d_in[13];
    const float* pr_w    = (const float*)d_in[14];
    const float* pr_b    = (const float*)d_in[15];
    const float* lnf_g   = (const float*)d_in[16];
    const float* lnf_b   = (const float*)d_in[17];
    const float* lm_w    = (const float*)d_in[18];
    float* out = (float*)d_out;

    float *px, *ph, *pqkv, *py, *pff, *pnll, *pval, *pfall;
    cudaGetSymbolAddress((void**)&px,   g_x);
    cudaGetSymbolAddress((void**)&ph,   g_h);
    cudaGetSymbolAddress((void**)&pqkv, g_qkv);
    cudaGetSymbolAddress((void**)&py,   g_y);
    cudaGetSymbolAddress((void**)&pff,  g_ff);
    cudaGetSymbolAddress((void**)&pnll, g_nll);
    cudaGetSymbolAddress((void**)&pval, g_val);
    cudaGetSymbolAddress((void**)&pfall, g_logits_fallback);

    const long long need_logits = (long long)Mv * Vv;
    float* logits = ((long long)out_size >= need_logits) ? out : pfall;
    float* loss_dst = ((long long)out_size >= need_logits + 1) ? (out + need_logits)
                    : (((long long)out_size < need_logits) ? out : nullptr);

    // embedding
    k_embed<<<(Mv * Dv + 255) / 256, 256>>>(idx, wte, wpe, px);

    dim3 gf(Tv / 64, Bv * Hv);

    for (int l = 0; l < Lv; l++) {
        const float* l1g = ln1_g + (size_t)l * Dv;
        const float* l1b = ln1_b + (size_t)l * Dv;
        const float* wq  = qkv_w + (size_t)l * Dv * D3v;
        const float* bq  = qkv_b + (size_t)l * D3v;
        const float* wo  = po_w  + (size_t)l * Dv * Dv;
        const float* bo  = po_b  + (size_t)l * Dv;
        const float* l2g = ln2_g + (size_t)l * Dv;
        const float* l2b = ln2_b + (size_t)l * Dv;
        const float* wf  = fc_w  + (size_t)l * Dv * FFv;
        const float* bf  = fc_b  + (size_t)l * FFv;
        const float* wp  = pr_w  + (size_t)l * FFv * Dv;
        const float* bp  = pr_b  + (size_t)l * Dv;

        // ln1
        k_ln<<<Mv, 256>>>(px, l1g, l1b, ph);
        // qkv = h @ wq + bq
        k_sgemm<<<dim3((D3v + BN - 1) / BN, Mv / BM), 256>>>(ph, wq, bq, nullptr, pqkv, Mv, D3v, Dv, 0);
        // fused attention
        k_flash<<<gf, 256>>>(pqkv, py);
        // x = x + y @ wo + bo
        k_sgemm<<<dim3((Dv + BN - 1) / BN, Mv / BM), 256>>>(py, wo, bo, px, px, Mv, Dv, Dv, 0);
        // ln2
        k_ln<<<Mv, 256>>>(px, l2g, l2b, ph);
        // ff = mgelu(h2 @ wf + bf)
        k_sgemm<<<dim3((FFv + BN - 1) / BN, Mv / BM), 256>>>(ph, wf, bf, nullptr, pff, Mv, FFv, Dv, 1);
        // x = x + ff @ wp + bp
        k_sgemm<<<dim3((Dv + BN - 1) / BN, Mv / BM), 256>>>(pff, wp, bp, px, px, Mv, Dv, FFv, 0);
    }

    // final layernorm + LM head
    k_ln<<<Mv, 256>>>(px, lnf_g, lnf_b, ph);
    k_sgemm<<<dim3((Vv + BN - 1) / BN, Mv / BM), 256>>>(ph, lm_w, nullptr, nullptr, logits, Mv, Vv, Dv, 0);

    // loss
    k_nll<<<Mv, 256>>>(logits, targets, pnll, pval);
    if (loss_dst) k_loss<<<1, 256>>>(pnll, pval, loss_dst);
}

// round 16
// speedup vs baseline: 1.5457x; 1.1309x over previous
#include <cuda_runtime.h>
#include <cuda_bf16.h>
#include <math.h>
#include <float.h>
#include <stdint.h>

// ---------------- problem constants ----------------
constexpr int Bv  = 2;
constexpr int Tv  = 1024;
constexpr int Lv  = 12;
constexpr int Hv  = 12;
constexpr int Dv  = 768;
constexpr int HDv = 64;
constexpr int FFv = 3072;
constexpr int Vv  = 50257;
constexpr int Mv  = Bv * Tv;          // 2048 rows
constexpr int D3v = 3 * Dv;           // 2304

// ---------------- scratch (static device memory; no allocations) ----------------
__device__ float g_x   [(size_t)Mv * Dv];
__device__ float g_h   [(size_t)Mv * Dv];
__device__ float g_qkv [(size_t)Mv * D3v];
__device__ float g_y   [(size_t)Mv * Dv];
__device__ float g_ff  [(size_t)Mv * FFv];
__device__ float g_nll [Mv];
__device__ float g_val [Mv];
__device__ float g_logits_fallback[(size_t)Mv * Vv];  // used only if d_out can't hold logits

// ---------------- helpers ----------------
__device__ __forceinline__ float mgelu_f(float x) {
    // NOTE: module uses 0.047715 (not the standard 0.044715)
    const float c0 = 0.7978845608028654f; // sqrt(2/pi)
    float x3 = x * x * x;
    return 0.5f * x * (1.0f + tanhf(c0 * (x + 0.047715f * x3)));
}

__device__ __forceinline__ float tf32_round(float x) {
    uint32_t u;
    asm("cvt.rna.tf32.f32 %0, %1;" : "=r"(u) : "f"(x));
    return __uint_as_float(u);
}

#define MMA_TF32(c, a0, a1, a2, a3, b0, b1)                                   \
    asm volatile(                                                             \
        "mma.sync.aligned.m16n8k8.row.col.f32.tf32.tf32.f32 "                 \
        "{%0,%1,%2,%3}, {%4,%5,%6,%7}, {%8,%9}, {%0,%1,%2,%3};"               \
        : "+f"((c)[0]), "+f"((c)[1]), "+f"((c)[2]), "+f"((c)[3])              \
        : "r"(a0), "r"(a1), "r"(a2), "r"(a3), "r"(b0), "r"(b1))

// ---------------- embedding ----------------
__global__ void k_embed(const int* __restrict__ idx,
                        const float* __restrict__ wte,
                        const float* __restrict__ wpe,
                        float* __restrict__ x) {
    int i = blockIdx.x * 256 + threadIdx.x;
    if (i >= Mv * Dv) return;
    int m = i / Dv, d = i % Dv;
    int t = m % Tv;
    x[i] = wte[(size_t)idx[m] * Dv + d] + wpe[(size_t)t * Dv + d];
}

// ---------------- layernorm (one block per row) ----------------
__global__ void k_ln(const float* __restrict__ x,
                     const float* __restrict__ g,
                     const float* __restrict__ b,
                     float* __restrict__ o) {
    int row = blockIdx.x;
    const float* xr = x + (size_t)row * Dv;
    __shared__ float red[256];
    int tid = threadIdx.x;

    float s = 0.f;
    for (int d = tid; d < Dv; d += 256) s += xr[d];
    red[tid] = s; __syncthreads();
    for (int st = 128; st > 0; st >>= 1) { if (tid < st) red[tid] += red[tid + st]; __syncthreads(); }
    float mean = red[0] / Dv;
    __syncthreads();

    float v = 0.f;
    for (int d = tid; d < Dv; d += 256) { float t = xr[d] - mean; v += t * t; }
    red[tid] = v; __syncthreads();
    for (int st = 128; st > 0; st >>= 1) { if (tid < st) red[tid] += red[tid + st]; __syncthreads(); }
    float inv = rsqrtf(red[0] / Dv + 1e-5f);

    float* orow = o + (size_t)row * Dv;
    for (int d = tid; d < Dv; d += 256)
        orow[d] = (xr[d] - mean) * inv * g[d] + b[d];
}

// ---------------- 3xTF32 tensor-core GEMM, double-buffered ----------------
// C[M,N] = epi( A[M,K] @ W[K,N] )   epi: +bias, optional mgelu, optional +res
// Two-stage smem pipeline: prefetch tile k+1 to regs while computing tile k.
// Math identical to verified single-buffer version.
#define BM 128
#define BN 128
#define BK 16
#define SPAD 4
// one array chunk = BK rows of (BM+SPAD) floats; 4 arrays (Ah,Al,Bh,Bl) / stage
#define GCH (BK * (BM + SPAD))
#define GST (4 * GCH)
constexpr int SMEM_GEMM_BYTES = 2 * GST * 4;   // 67584

#define sAh(s,k,m) smem_dyn[(s)*GST + 0*GCH + (k)*(BM+SPAD) + (m)]
#define sAl(s,k,m) smem_dyn[(s)*GST + 1*GCH + (k)*(BM+SPAD) + (m)]
#define sBh(s,k,n) smem_dyn[(s)*GST + 2*GCH + (k)*(BN+SPAD) + (n)]
#define sBl(s,k,n) smem_dyn[(s)*GST + 3*GCH + (k)*(BN+SPAD) + (n)]

__global__ __launch_bounds__(256) void k_sgemm(
    const float* __restrict__ A, const float* __restrict__ W,
    const float* __restrict__ bias, const float* __restrict__ res,
    float* __restrict__ C, int M, int N, int K, int act) {

    extern __shared__ float smem_dyn[];

    int m0 = blockIdx.y * BM, n0 = blockIdx.x * BN;
    int tid  = threadIdx.x;
    int lane = tid & 31, warp = tid >> 5;
    int warp_m = warp & 3;
    int warp_n = warp >> 2;
    int rowq = lane >> 2;
    int kr   = lane & 3;
    bool vec_ok = ((N & 3) == 0);

    float acc[2][8][4];
#pragma unroll
    for (int i = 0; i < 2; i++)
#pragma unroll
        for (int j = 0; j < 8; j++)
#pragma unroll
            for (int q = 0; q < 4; q++) acc[i][j][q] = 0.f;

    int a_r = tid >> 2, a_c4 = (tid & 3) * 4;
    int b_r = tid >> 5, b_c4 = (tid & 31) * 4;
    int s_k = tid >> 7, s_n = tid & 127;

    // prefetch registers
    float4 pa[2];
    float4 pb[2];
    float  pbs[8];

    // ---- load helpers (gmem -> regs) ----
    auto load_regs = [&](int k0) {
#pragma unroll
        for (int it = 0; it < 2; it++)
            pa[it] = *(const float4*)&A[(size_t)(m0 + a_r + 64 * it) * K + k0 + a_c4];
        if (vec_ok) {
#pragma unroll
            for (int it = 0; it < 2; it++)
                pb[it] = *(const float4*)&W[(size_t)(k0 + b_r + 8 * it) * N + n0 + b_c4];
        } else {
#pragma unroll
            for (int it = 0; it < 8; it++) {
                int k = s_k + 2 * it;
                int n = n0 + s_n;
                pbs[it] = (n < N) ? W[(size_t)(k0 + k) * N + n] : 0.f;
            }
        }
    };
    // ---- split + store (regs -> smem stage s) ----
    auto store_stage = [&](int s) {
#pragma unroll
        for (int it = 0; it < 2; it++) {
            int m = a_r + 64 * it;
            float c[4] = {pa[it].x, pa[it].y, pa[it].z, pa[it].w};
#pragma unroll
            for (int j = 0; j < 4; j++) {
                float hi = tf32_round(c[j]);
                sAh(s, a_c4 + j, m) = hi;
                sAl(s, a_c4 + j, m) = tf32_round(c[j] - hi);
            }
        }
        if (vec_ok) {
#pragma unroll
            for (int it = 0; it < 2; it++) {
                int k = b_r + 8 * it;
                float c[4] = {pb[it].x, pb[it].y, pb[it].z, pb[it].w};
#pragma unroll
                for (int j = 0; j < 4; j++) {
                    float hi = tf32_round(c[j]);
                    sBh(s, k, b_c4 + j) = hi;
                    sBl(s, k, b_c4 + j) = tf32_round(c[j] - hi);
                }
            }
        } else {
#pragma unroll
            for (int it = 0; it < 8; it++) {
                int k = s_k + 2 * it;
                float hi = tf32_round(pbs[it]);
                sBh(s, k, s_n) = hi;
                sBl(s, k, s_n) = tf32_round(pbs[it] - hi);
            }
        }
    };

    // prologue: stage 0
    load_regs(0);
    store_stage(0);
    __syncthreads();

    int buf = 0;
    for (int k0 = 0; k0 < K; k0 += BK) {
        bool has_next = (k0 + BK) < K;
        if (has_next) load_regs(k0 + BK);   // overlap with compute below

        // ---- compute on stage buf ----
#pragma unroll
        for (int kk = 0; kk < BK; kk += 8) {
            uint32_t ahf[2][4], alf[2][4];
#pragma unroll
            for (int mt = 0; mt < 2; mt++) {
                int mb = warp_m * 32 + mt * 16 + rowq;
                ahf[mt][0] = __float_as_uint(sAh(buf, kk + kr    , mb    ));
                ahf[mt][1] = __float_as_uint(sAh(buf, kk + kr    , mb + 8));
                ahf[mt][2] = __float_as_uint(sAh(buf, kk + kr + 4, mb    ));
                ahf[mt][3] = __float_as_uint(sAh(buf, kk + kr + 4, mb + 8));
                alf[mt][0] = __float_as_uint(sAl(buf, kk + kr    , mb    ));
                alf[mt][1] = __float_as_uint(sAl(buf, kk + kr    , mb + 8));
                alf[mt][2] = __float_as_uint(sAl(buf, kk + kr + 4, mb    ));
                alf[mt][3] = __float_as_uint(sAl(buf, kk + kr + 4, mb + 8));
            }
#pragma unroll
            for (int nt = 0; nt < 8; nt++) {
                int nb = warp_n * 64 + nt * 8 + rowq;
                uint32_t bh0 = __float_as_uint(sBh(buf, kk + kr    , nb));
                uint32_t bh1 = __float_as_uint(sBh(buf, kk + kr + 4, nb));
                uint32_t bl0 = __float_as_uint(sBl(buf, kk + kr    , nb));
                uint32_t bl1 = __float_as_uint(sBl(buf, kk + kr + 4, nb));
#pragma unroll
                for (int mt = 0; mt < 2; mt++) {
                    MMA_TF32(acc[mt][nt], ahf[mt][0], ahf[mt][1], ahf[mt][2], ahf[mt][3], bh0, bh1);
                    MMA_TF32(acc[mt][nt], ahf[mt][0], ahf[mt][1], ahf[mt][2], ahf[mt][3], bl0, bl1);
                    MMA_TF32(acc[mt][nt], alf[mt][0], alf[mt][1], alf[mt][2], alf[mt][3], bh0, bh1);
                }
            }
        }

        if (has_next) {
            store_stage(buf ^ 1);   // write other stage (no reader conflict)
            __syncthreads();
            buf ^= 1;
        }
    }

    // ---- epilogue: m16n8 accumulator layout ----
    int colq = (lane & 3) * 2;
#pragma unroll
    for (int mt = 0; mt < 2; mt++) {
        int r0 = m0 + warp_m * 32 + mt * 16 + rowq;
#pragma unroll
        for (int nt = 0; nt < 8; nt++) {
            int c0 = n0 + warp_n * 64 + nt * 8 + colq;
#pragma unroll
            for (int half = 0; half < 2; half++) {
                int r = r0 + 8 * half;
#pragma unroll
                for (int cc = 0; cc < 2; cc++) {
                    int c = c0 + cc;
                    if (c < N) {
                        float v = acc[mt][nt][half * 2 + cc];
                        if (bias) v += bias[c];
                        if (act) v = mgelu_f(v);
                        if (res) v += res[(size_t)r * N + c];
                        C[(size_t)r * N + c] = v;
                    }
                }
            }
        }
    }
}

// ---------------- fused flash attention (fp32) ----------------
__global__ __launch_bounds__(256) void k_flash(const float* __restrict__ qkv,
                                               float* __restrict__ y) {
    __shared__ float Qt[64][64];   // [d][m]
    __shared__ float KPt[64][64];  // K phase: [d][n]; P phase: [n][m]
    __shared__ float Vs[64][64];   // [n][d]

    int bh = blockIdx.y;
    int b = bh / Hv, h = bh % Hv;
    int qb = gridDim.x - 1 - blockIdx.x;   // big blocks first
    int tid = threadIdx.x;
    int tx = tid & 15, ty = tid >> 4;

    int lr = tid >> 2;              // load row 0..63
    int lc = (tid & 3) * 16;        // 16-col chunk

    {
        const float* src = qkv + (size_t)(b * Tv + qb * 64 + lr) * D3v + h * HDv;
#pragma unroll
        for (int j = 0; j < 4; j++) {
            float4 v = *(const float4*)&src[lc + j * 4];
            Qt[lc + j * 4 + 0][lr] = v.x;
            Qt[lc + j * 4 + 1][lr] = v.y;
            Qt[lc + j * 4 + 2][lr] = v.z;
            Qt[lc + j * 4 + 3][lr] = v.w;
        }
    }

    float O[4][4];
    float m_i[4], l_i[4];
#pragma unroll
    for (int i = 0; i < 4; i++) {
        m_i[i] = -FLT_MAX; l_i[i] = 0.f;
#pragma unroll
        for (int j = 0; j < 4; j++) O[i][j] = 0.f;
    }

    for (int kb = 0; kb <= qb; kb++) {
        {
            const float* ks = qkv + (size_t)(b * Tv + kb * 64 + lr) * D3v + Dv + h * HDv;
            const float* vs = qkv + (size_t)(b * Tv + kb * 64 + lr) * D3v + 2 * Dv + h * HDv;
#pragma unroll
            for (int j = 0; j < 4; j++) {
                float4 kv = *(const float4*)&ks[lc + j * 4];
                KPt[lc + j * 4 + 0][lr] = kv.x;
                KPt[lc + j * 4 + 1][lr] = kv.y;
                KPt[lc + j * 4 + 2][lr] = kv.z;
                KPt[lc + j * 4 + 3][lr] = kv.w;
                *(float4*)&Vs[lr][lc + j * 4] = *(const float4*)&vs[lc + j * 4];
            }
        }
        __syncthreads();

        float S[4][4];
#pragma unroll
        for (int i = 0; i < 4; i++)
#pragma unroll
            for (int j = 0; j < 4; j++) S[i][j] = 0.f;
        for (int kk = 0; kk < 64; kk++) {
            float4 a4 = *(const float4*)&Qt[kk][ty * 4];
            float4 b4 = *(const float4*)&KPt[kk][tx * 4];
            float a[4] = {a4.x, a4.y, a4.z, a4.w};
            float bb[4] = {b4.x, b4.y, b4.z, b4.w};
#pragma unroll
            for (int i = 0; i < 4; i++)
#pragma unroll
                for (int j = 0; j < 4; j++) S[i][j] += a[i] * bb[j];
        }

#pragma unroll
        for (int i = 0; i < 4; i++)
#pragma unroll
            for (int j = 0; j < 4; j++) {
                float s = S[i][j] * 0.125f;   // 1/sqrt(64)
                if (kb == qb && (tx * 4 + j) > (ty * 4 + i)) s = -1e30f;
                S[i][j] = s;
            }

#pragma unroll
        for (int i = 0; i < 4; i++) {
            float mx = fmaxf(fmaxf(S[i][0], S[i][1]), fmaxf(S[i][2], S[i][3]));
#pragma unroll
            for (int off = 8; off > 0; off >>= 1)
                mx = fmaxf(mx, __shfl_xor_sync(0xffffffffu, mx, off));
            float m_new = fmaxf(m_i[i], mx);
            float corr = expf(m_i[i] - m_new);
            float rs = 0.f;
#pragma unroll
            for (int j = 0; j < 4; j++) {
                float p = expf(S[i][j] - m_new);
                S[i][j] = p;
                rs += p;
            }
#pragma unroll
            for (int off = 8; off > 0; off >>= 1)
                rs += __shfl_xor_sync(0xffffffffu, rs, off);
            l_i[i] = l_i[i] * corr + rs;
            m_i[i] = m_new;
#pragma unroll
            for (int j = 0; j < 4; j++) O[i][j] *= corr;
        }
        __syncthreads();

#pragma unroll
        for (int i = 0; i < 4; i++)
#pragma unroll
            for (int j = 0; j < 4; j++)
                KPt[tx * 4 + j][ty * 4 + i] = S[i][j];
        __syncthreads();

        for (int kk = 0; kk < 64; kk++) {
            float4 p4 = *(const float4*)&KPt[kk][ty * 4];
            float4 v4 = *(const float4*)&Vs[kk][tx * 4];
            float p[4] = {p4.x, p4.y, p4.z, p4.w};
            float vv[4] = {v4.x, v4.y, v4.z, v4.w};
#pragma unroll
            for (int i = 0; i < 4; i++)
#pragma unroll
                for (int j = 0; j < 4; j++) O[i][j] += p[i] * vv[j];
        }
        __syncthreads();
    }

#pragma unroll
    for (int i = 0; i < 4; i++) {
        float inv = 1.0f / l_i[i];
        int row = b * Tv + qb * 64 + ty * 4 + i;
#pragma unroll
        for (int j = 0; j < 4; j++)
            y[(size_t)row * Dv + h * HDv + tx * 4 + j] = O[i][j] * inv;
    }
}

// ---------------- cross-entropy: per-row logsumexp ----------------
__global__ void k_nll(const float* __restrict__ logits, const int* __restrict__ targets,
                      float* __restrict__ nll, float* __restrict__ val) {
    int row = blockIdx.x;
    const float* lr = logits + (size_t)row * Vv;
    __shared__ float red[256];
    int tid = threadIdx.x;

    float mx = -FLT_MAX;
    for (int i = tid; i < Vv; i += 256) mx = fmaxf(mx, lr[i]);
    red[tid] = mx; __syncthreads();
    for (int st = 128; st > 0; st >>= 1) { if (tid < st) red[tid] = fmaxf(red[tid], red[tid + st]); __syncthreads(); }
    mx = red[0];
    __syncthreads();

    float s = 0.f;
    for (int i = tid; i < Vv; i += 256) s += expf(lr[i] - mx);
    red[tid] = s; __syncthreads();
    for (int st = 128; st > 0; st >>= 1) { if (tid < st) red[tid] += red[tid + st]; __syncthreads(); }

    if (tid == 0) {
        int tgt = targets[row];
        bool ok = (tgt >= 0);
        float lse = mx + logf(red[0]);
        nll[row] = ok ? (lse - lr[tgt]) : 0.f;
        val[row] = ok ? 1.f : 0.f;
    }
}

__global__ void k_loss(const float* __restrict__ nll, const float* __restrict__ val,
                       float* __restrict__ out) {
    __shared__ float rn[256], rv[256];
    int tid = threadIdx.x;
    float sn = 0.f, sv = 0.f;
    for (int i = tid; i < Mv; i += 256) { sn += nll[i]; sv += val[i]; }
    rn[tid] = sn; rv[tid] = sv; __syncthreads();
    for (int st = 128; st > 0; st >>= 1) {
        if (tid < st) { rn[tid] += rn[tid + st]; rv[tid] += rv[tid + st]; }
        __syncthreads();
    }
    if (tid == 0) out[0] = rn[0] / fmaxf(rv[0], 1.f);
}

// ---------------- host driver ----------------
extern "C" void kernel_launch(void* const* d_in, const int* in_sizes, int n_in,
                              void* d_out, int out_size) {
    const int*   idx     = (const int*)  d_in[0];
    const int*   targets = (const int*)  d_in[1];
    const float* wte     = (const float*)d_in[2];
    const float* wpe     = (const float*)d_in[3];
    const float* ln1_g   = (const float*)d_in[4];
    const float* ln1_b   = (const float*)d_in[5];
    const float* qkv_w   = (const float*)d_in[6];
    const float* qkv_b   = (const float*)d_in[7];
    const float* po_w    = (const float*)d_in[8];
    const float* po_b    = (const float*)d_in[9];
    const float* ln2_g   = (const float*)d_in[10];
    const float* ln2_b   = (const float*)d_in[11];
    const float* fc_w    = (const float*)d_in[12];
    const float* fc_b    = (const float*)d_in[13];
    const float* pr_w    = (const float*)d_in[14];
    const float* pr_b    = (const float*)d_in[15];
    const float* lnf_g   = (const float*)d_in[16];
    const float* lnf_b   = (const float*)d_in[17];
    const float* lm_w    = (const float*)d_in[18];
    float* out = (float*)d_out;

    // allow 67.6 KB dynamic smem for the double-buffered GEMM (idempotent)
    cudaFuncSetAttribute(k_sgemm, cudaFuncAttributeMaxDynamicSharedMemorySize, SMEM_GEMM_BYTES);

    float *px, *ph, *pqkv, *py, *pff, *pnll, *pval, *pfall;
    cudaGetSymbolAddress((void**)&px,   g_x);
    cudaGetSymbolAddress((void**)&ph,   g_h);
    cudaGetSymbolAddress((void**)&pqkv, g_qkv);
    cudaGetSymbolAddress((void**)&py,   g_y);
    cudaGetSymbolAddress((void**)&pff,  g_ff);
    cudaGetSymbolAddress((void**)&pnll, g_nll);
    cudaGetSymbolAddress((void**)&pval, g_val);
    cudaGetSymbolAddress((void**)&pfall, g_logits_fallback);

    const long long need_logits = (long long)Mv * Vv;
    float* logits = ((long long)out_size >= need_logits) ? out : pfall;
    float* loss_dst = ((long long)out_size >= need_logits + 1) ? (out + need_logits)
                    : (((long long)out_size < need_logits) ? out : nullptr);

    // embedding
    k_embed<<<(Mv * Dv + 255) / 256, 256>>>(idx, wte, wpe, px);

    dim3 gf(Tv / 64, Bv * Hv);

    for (int l = 0; l < Lv; l++) {
        const float* l1g = ln1_g + (size_t)l * Dv;
        const float* l1b = ln1_b + (size_t)l * Dv;
        const float* wq  = qkv_w + (size_t)l * Dv * D3v;
        const float* bq  = qkv_b + (size_t)l * D3v;
        const float* wo  = po_w  + (size_t)l * Dv * Dv;
        const float* bo  = po_b  + (size_t)l * Dv;
        const float* l2g = ln2_g + (size_t)l * Dv;
        const float* l2b = ln2_b + (size_t)l * Dv;
        const float* wf  = fc_w  + (size_t)l * Dv * FFv;
        const float* bf  = fc_b  + (size_t)l * FFv;
        const float* wp  = pr_w  + (size_t)l * FFv * Dv;
        const float* bp  = pr_b  + (size_t)l * Dv;

        // ln1
        k_ln<<<Mv, 256>>>(px, l1g, l1b, ph);
        // qkv = h @ wq + bq
        k_sgemm<<<dim3((D3v + BN - 1) / BN, Mv / BM), 256, SMEM_GEMM_BYTES>>>(ph, wq, bq, nullptr, pqkv, Mv, D3v, Dv, 0);
        // fused attention
        k_flash<<<gf, 256>>>(pqkv, py);
        // x = x + y @ wo + bo
        k_sgemm<<<dim3((Dv + BN - 1) / BN, Mv / BM), 256, SMEM_GEMM_BYTES>>>(py, wo, bo, px, px, Mv, Dv, Dv, 0);
        // ln2
        k_ln<<<Mv, 256>>>(px, l2g, l2b, ph);
        // ff = mgelu(h2 @ wf + bf)
        k_sgemm<<<dim3((FFv + BN - 1) / BN, Mv / BM), 256, SMEM_GEMM_BYTES>>>(ph, wf, bf, nullptr, pff, Mv, FFv, Dv, 1);
        // x = x + ff @ wp + bp
        k_sgemm<<<dim3((Dv + BN - 1) / BN, Mv / BM), 256, SMEM_GEMM_BYTES>>>(pff, wp, bp, px, px, Mv, Dv, FFv, 0);
    }

    // final layernorm + LM head
    k_ln<<<Mv, 256>>>(px, lnf_g, lnf_b, ph);
    k_sgemm<<<dim3((Vv + BN - 1) / BN, Mv / BM), 256, SMEM_GEMM_BYTES>>>(ph, lm_w, nullptr, nullptr, logits, Mv, Vv, Dv, 0);

    // loss
    k_nll<<<Mv, 256>>>(logits, targets, pnll, pval);
    if (loss_dst) k_loss<<<1, 256>>>(pnll, pval, loss_dst);
}